// round 5
// baseline (speedup 1.0000x reference)
#include <cuda_runtime.h>
#include <cuda_bf16.h>
#include <cstdint>

#define NRES  384
#define NSEQ  256
#define NFEAT 64
#define NPROJ 32
#define NOUT  128
#define ICDIM (NRES*NPROJ)          // 12288
#define NPAIR (NRES*NRES)           // 147456
#define CD    (NPROJ*NPROJ)         // 1024
#define LN_EPS 1e-5f

// ------------------------- scratch (device globals) -------------------------
__device__ __nv_bfloat16 g_Lt[(size_t)ICDIM*NSEQ];   // [m=(i,c)][s]  K-major
__device__ __nv_bfloat16 g_Rt[(size_t)ICDIM*NSEQ];   // [n=(j,d)][s]  K-major
__device__ __nv_bfloat16 g_O [(size_t)NPAIR*CD];     // [(i,j)][(c,d)]
__device__ __nv_bfloat16 g_Wob[NOUT*CD];             // Wo bf16 [o][cd]
__device__ float         g_normv[NPAIR];

// ------------------------- helpers -------------------------
__device__ __forceinline__ uint32_t smem_u32(const void* p){
    uint32_t a;
    asm("{ .reg .u64 t; cvta.to.shared.u64 t, %1; cvt.u32.u64 %0, t; }":"=r"(a):"l"(p));
    return a;
}
__device__ __forceinline__ void ldsm4(uint32_t& r0, uint32_t& r1, uint32_t& r2, uint32_t& r3, uint32_t a){
    asm volatile("ldmatrix.sync.aligned.m8n8.x4.shared.b16 {%0,%1,%2,%3}, [%4];"
        : "=r"(r0),"=r"(r1),"=r"(r2),"=r"(r3) : "r"(a));
}
__device__ __forceinline__ void mma16816(float* c, const uint32_t* a, uint32_t b0, uint32_t b1){
    asm volatile("mma.sync.aligned.m16n8k16.row.col.f32.bf16.bf16.f32 "
        "{%0,%1,%2,%3}, {%4,%5,%6,%7}, {%8,%9}, {%0,%1,%2,%3};"
        : "+f"(c[0]),"+f"(c[1]),"+f"(c[2]),"+f"(c[3])
        : "r"(a[0]),"r"(a[1]),"r"(a[2]),"r"(a[3]),"r"(b0),"r"(b1));
}
__device__ __forceinline__ uint32_t packbf2(float a, float b){
    __nv_bfloat162 h = __floats2bfloat162_rn(a, b);
    return *(uint32_t*)&h;
}
#define CP16(dst, src) asm volatile("cp.async.cg.shared.global [%0], [%1], 16;" \
    :: "r"(dst), "l"(src) : "memory")
#define CP_COMMIT() asm volatile("cp.async.commit_group;" ::: "memory")
#define CP_WAIT(n)  asm volatile("cp.async.wait_group %0;" :: "n"(n) : "memory")

// ---------------------------------------------------------------------------
// prep: LN + projections + mask; write transposed bf16 g_Lt/g_Rt.
// grid=384 (block per residue i), 256 threads (thread per s).
// ---------------------------------------------------------------------------
#define PREP_SMEM (4096*4 + 2*8192*2)   // 49152
__global__ void __launch_bounds__(256,2)
prep_kernel(const float* __restrict__ M, const float* __restrict__ mask,
            const float* __restrict__ gamma, const float* __restrict__ beta,
            const float* __restrict__ Wa, const float* __restrict__ ba,
            const float* __restrict__ Wb, const float* __restrict__ bb)
{
    extern __shared__ float ps[];
    float* sWa = ps;
    float* sWb = ps + 2048;
    __nv_bfloat16* sLb = (__nv_bfloat16*)(ps + 4096);  // [32][256]
    __nv_bfloat16* sRb = sLb + 8192;

    const int i = blockIdx.x;
    const int tid = threadIdx.x;
    for (int u = tid; u < NPROJ*NFEAT; u += 256){ sWa[u] = Wa[u]; sWb[u] = Wb[u]; }

    const int s = tid;
    const float4* mr = (const float4*)(M + ((size_t)s*NRES + i)*NFEAT);
    float4 mn[16];
    float s1 = 0.f, s2 = 0.f;
    #pragma unroll
    for (int q = 0; q < 16; q++){
        float4 v = mr[q]; mn[q] = v;
        s1 += v.x + v.y + v.z + v.w;
        s2 += v.x*v.x + v.y*v.y + v.z*v.z + v.w*v.w;
    }
    float mu  = s1 * (1.f/64.f);
    float var = s2 * (1.f/64.f) - mu*mu;
    float inv = rsqrtf(var + LN_EPS);
    const float4* g4 = (const float4*)gamma;
    const float4* b4 = (const float4*)beta;
    #pragma unroll
    for (int q = 0; q < 16; q++){
        float4 gg = g4[q], be = b4[q];
        mn[q].x = (mn[q].x - mu)*inv*gg.x + be.x;
        mn[q].y = (mn[q].y - mu)*inv*gg.y + be.y;
        mn[q].z = (mn[q].z - mu)*inv*gg.z + be.z;
        mn[q].w = (mn[q].w - mu)*inv*gg.w + be.w;
    }
    const float msk = mask[(size_t)s*NRES + i];
    __syncthreads();

    #pragma unroll 4
    for (int c = 0; c < NPROJ; c++){
        float accA = ba[c], accB = bb[c];
        const float4* wa = (const float4*)(sWa + c*NFEAT);
        const float4* wb = (const float4*)(sWb + c*NFEAT);
        #pragma unroll
        for (int q = 0; q < 16; q++){
            float4 w1 = wa[q], w2 = wb[q], v = mn[q];
            accA += v.x*w1.x + v.y*w1.y + v.z*w1.z + v.w*w1.w;
            accB += v.x*w2.x + v.y*w2.y + v.z*w2.z + v.w*w2.w;
        }
        sLb[c*256 + s] = __float2bfloat16(msk*accA);
        sRb[c*256 + s] = __float2bfloat16(msk*accB);
    }
    __syncthreads();

    for (int u = tid; u < NPROJ*128; u += 256){
        int c = u >> 7, sp = (u & 127) << 1;
        *(uint32_t*)(g_Lt + ((size_t)(i*NPROJ + c))*NSEQ + sp) = *(const uint32_t*)(sLb + c*256 + sp);
        *(uint32_t*)(g_Rt + ((size_t)(i*NPROJ + c))*NSEQ + sp) = *(const uint32_t*)(sRb + c*256 + sp);
    }
}

// ---------------------------------------------------------------------------
__global__ void norm_kernel(const float* __restrict__ mask)
{
    const int i = blockIdx.x, j = threadIdx.x;
    float acc = 0.0f;
    for (int s = 0; s < NSEQ; s++)
        acc += mask[s*NRES + i] * mask[s*NRES + j];
    g_normv[i*NRES + j] = acc;
}

__global__ void wconv_kernel(const float* __restrict__ Wo)
{
    int idx = blockIdx.x*256 + threadIdx.x;
    g_Wob[idx] = __float2bfloat16(Wo[idx]);
}

// ---------------------------------------------------------------------------
// gemm1: O[128x128] = Lt[it*128..] @ Rt[jt*128..]^T, K=256.
// cp.async 2-stage ping-pong over 4 k-chunks of 64. 32KB/stage.
// grid=(96,96), 256 threads, occ 2.
// ---------------------------------------------------------------------------
#define G1_SMEM (2*32768)
__global__ void __launch_bounds__(256,2) gemm1_kernel()
{
    extern __shared__ char sm1[];
    const int tid = threadIdx.x, lane = tid & 31, w = tid >> 5;
    const int it = blockIdx.y, jt = blockIdx.x;
    const int wr = w >> 2, wc = w & 3;
    const int m0 = wr*64, n0 = wc*32;
    const int lo7 = lane & 7, hi = lane >> 4, l15 = lane & 15;

    const uint32_t sb = smem_u32(sm1);
    const int lrow = tid >> 1;                  // 0..127 (2 threads per row)
    const int lc0  = (tid & 1) << 2;            // 0 or 4 (4 uint4 each)

    // per-stage: A[128][64k] 16KB + B same at +16384; stage stride 32768
    auto stage_ptrs = [&](int kc, int s, int q, uint32_t& da, uint32_t& db,
                          const void*& ga, const void*& gb){
        int c = lc0 + q;
        int cp = c ^ (lrow & 7);
        da = sb + s*32768 + lrow*128 + cp*16;
        db = da + 16384;
        ga = g_Lt + ((size_t)(it*128 + lrow))*NSEQ + kc*64 + c*8;
        gb = g_Rt + ((size_t)(jt*128 + lrow))*NSEQ + kc*64 + c*8;
    };
    #define G1_LOAD(kc, s) do {                                   \
        _Pragma("unroll")                                         \
        for (int q = 0; q < 4; q++){                              \
            uint32_t da, db; const void *ga, *gb;                 \
            stage_ptrs(kc, s, q, da, db, ga, gb);                 \
            CP16(da, ga); CP16(db, gb);                           \
        }                                                         \
    } while(0)

    float acc[4][4][4];
    #pragma unroll
    for (int a = 0; a < 4; a++)
        #pragma unroll
        for (int b = 0; b < 4; b++)
            #pragma unroll
            for (int c = 0; c < 4; c++) acc[a][b][c] = 0.f;

    G1_LOAD(0, 0); CP_COMMIT();

    #pragma unroll 1
    for (int kc = 0; kc < 4; kc++){
        if (kc < 3){ G1_LOAD(kc+1, (kc+1)&1); CP_COMMIT(); CP_WAIT(1); }
        else CP_WAIT(0);
        __syncthreads();
        const uint32_t sA = sb + (kc&1)*32768;
        const uint32_t sB = sA + 16384;
        #pragma unroll
        for (int ks = 0; ks < 4; ks++){
            int ch = ((ks*2 + hi) ^ lo7) << 4;
            uint32_t a[4][4], b[2][4];
            #pragma unroll
            for (int mt = 0; mt < 4; mt++)
                ldsm4(a[mt][0],a[mt][1],a[mt][2],a[mt][3],
                      sA + (m0 + mt*16 + l15)*128 + ch);
            #pragma unroll
            for (int nb = 0; nb < 2; nb++)
                ldsm4(b[nb][0],b[nb][1],b[nb][2],b[nb][3],
                      sB + (n0 + nb*16 + l15)*128 + ch);
            #pragma unroll
            for (int mt = 0; mt < 4; mt++){
                #pragma unroll
                for (int nb = 0; nb < 2; nb++){
                    mma16816(acc[mt][nb*2],   a[mt], b[nb][0], b[nb][2]);
                    mma16816(acc[mt][nb*2+1], a[mt], b[nb][1], b[nb][3]);
                }
            }
        }
        __syncthreads();
    }

    // epilogue -> g_O[(i*384+j)*1024 + c*32 + d] bf16
    const int rbase = lane >> 2, cpair = (lane & 3)*2;
    const int j = jt*4 + wc;
    #pragma unroll
    for (int mt = 0; mt < 4; mt++){
        int mg0 = it*128 + m0 + mt*16 + rbase;
        int mg1 = mg0 + 8;
        size_t base0 = (((size_t)(mg0 >> 5)*NRES + j) << 10) + ((mg0 & 31) << 5);
        size_t base1 = (((size_t)(mg1 >> 5)*NRES + j) << 10) + ((mg1 & 31) << 5);
        #pragma unroll
        for (int nt = 0; nt < 4; nt++){
            int d = nt*8 + cpair;
            *(uint32_t*)(g_O + base0 + d) = packbf2(acc[mt][nt][0], acc[mt][nt][1]);
            *(uint32_t*)(g_O + base1 + d) = packbf2(acc[mt][nt][2], acc[mt][nt][3]);
        }
    }
}

// ---------------------------------------------------------------------------
// gemm2: Z[m,o] = sum_k O[m,k]*Wob[o,k], m-tile 128, o=128, K=1024.
// cp.async 2-stage ping-pong over 16 k-chunks of 64. Fused epilogue.
// grid=1152, 256 threads, occ 2.
// ---------------------------------------------------------------------------
#define G2_SMEM (2*32768)
__global__ void __launch_bounds__(256,2)
gemm2_kernel(const float* __restrict__ Zraw, const float* __restrict__ bo,
             float* __restrict__ out)
{
    extern __shared__ char sm2[];
    __shared__ float sbo[NOUT];
    const int tid = threadIdx.x, lane = tid & 31, w = tid >> 5;
    const int m0 = blockIdx.x * 128;
    const int wr = w >> 2, wc = w & 3;
    const int mw0 = wr*64, o0 = wc*32;
    const int lo7 = lane & 7, hi = lane >> 4, l15 = lane & 15;

    const uint32_t sb = smem_u32(sm2);
    if (tid < NOUT) sbo[tid] = bo[tid];

    const int lrow = tid >> 1;
    const int lc0  = (tid & 1) << 2;

    #define G2_LOAD(kc, s) do {                                               \
        _Pragma("unroll")                                                     \
        for (int q = 0; q < 4; q++){                                          \
            int c = lc0 + q;                                                  \
            int cp = c ^ (lrow & 7);                                          \
            uint32_t da = sb + (s)*32768 + lrow*128 + cp*16;                  \
            CP16(da, (const void*)(g_O + (size_t)(m0 + lrow)*CD + (kc)*64 + c*8)); \
            CP16(da + 16384, (const void*)(g_Wob + (size_t)lrow*CD + (kc)*64 + c*8)); \
        }                                                                     \
    } while(0)

    float acc[4][4][4];
    #pragma unroll
    for (int a = 0; a < 4; a++)
        #pragma unroll
        for (int b = 0; b < 4; b++)
            #pragma unroll
            for (int c = 0; c < 4; c++) acc[a][b][c] = 0.f;

    G2_LOAD(0, 0); CP_COMMIT();

    #pragma unroll 1
    for (int kc = 0; kc < 16; kc++){
        if (kc < 15){ G2_LOAD(kc+1, (kc+1)&1); CP_COMMIT(); CP_WAIT(1); }
        else CP_WAIT(0);
        __syncthreads();
        const uint32_t sA = sb + (kc&1)*32768;
        const uint32_t sB = sA + 16384;
        #pragma unroll
        for (int ks = 0; ks < 4; ks++){
            int ch = ((ks*2 + hi) ^ lo7) << 4;
            uint32_t a[4][4], b[2][4];
            #pragma unroll
            for (int mt = 0; mt < 4; mt++)
                ldsm4(a[mt][0],a[mt][1],a[mt][2],a[mt][3],
                      sA + (mw0 + mt*16 + l15)*128 + ch);
            #pragma unroll
            for (int nb = 0; nb < 2; nb++)
                ldsm4(b[nb][0],b[nb][1],b[nb][2],b[nb][3],
                      sB + (o0 + nb*16 + l15)*128 + ch);
            #pragma unroll
            for (int mt = 0; mt < 4; mt++){
                #pragma unroll
                for (int nb = 0; nb < 2; nb++){
                    mma16816(acc[mt][nb*2],   a[mt], b[nb][0], b[nb][2]);
                    mma16816(acc[mt][nb*2+1], a[mt], b[nb][1], b[nb][3]);
                }
            }
        }
        __syncthreads();
    }

    // fused epilogue
    const int rbase = lane >> 2, cpair = (lane & 3)*2;
    #pragma unroll
    for (int mt = 0; mt < 4; mt++){
        int mA = m0 + mw0 + mt*16 + rbase;
        int mB = mA + 8;
        float invA = 1.0f / (0.001f + g_normv[mA]);
        float invB = 1.0f / (0.001f + g_normv[mB]);
        #pragma unroll
        for (int nt = 0; nt < 4; nt++){
            int o = o0 + nt*8 + cpair;
            float b0 = sbo[o], b1 = sbo[o+1];
            float2 zA = *(const float2*)(Zraw + (size_t)mA*NOUT + o);
            float2 zB = *(const float2*)(Zraw + (size_t)mB*NOUT + o);
            float2 rA, rB;
            rA.x = (acc[mt][nt][0] + b0)*invA + zA.x;
            rA.y = (acc[mt][nt][1] + b1)*invA + zA.y;
            rB.x = (acc[mt][nt][2] + b0)*invB + zB.x;
            rB.y = (acc[mt][nt][3] + b1)*invB + zB.y;
            *(float2*)(out + (size_t)mA*NOUT + o) = rA;
            *(float2*)(out + (size_t)mB*NOUT + o) = rB;
        }
    }
}

// ---------------------------------------------------------------------------
extern "C" void kernel_launch(void* const* d_in, const int* in_sizes, int n_in,
                              void* d_out, int out_size)
{
    const float* M     = (const float*)d_in[0];
    const float* mask  = (const float*)d_in[1];
    const float* Zraw  = (const float*)d_in[2];
    const float* gamma = (const float*)d_in[3];
    const float* beta  = (const float*)d_in[4];
    const float* Wa    = (const float*)d_in[5];
    const float* ba    = (const float*)d_in[6];
    const float* Wb    = (const float*)d_in[7];
    const float* bb    = (const float*)d_in[8];
    const float* Wo    = (const float*)d_in[9];
    const float* bo    = (const float*)d_in[10];
    float* out = (float*)d_out;

    cudaFuncSetAttribute(prep_kernel,  cudaFuncAttributeMaxDynamicSharedMemorySize, PREP_SMEM);
    cudaFuncSetAttribute(gemm1_kernel, cudaFuncAttributeMaxDynamicSharedMemorySize, G1_SMEM);
    cudaFuncSetAttribute(gemm2_kernel, cudaFuncAttributeMaxDynamicSharedMemorySize, G2_SMEM);

    prep_kernel<<<NRES, 256, PREP_SMEM>>>(M, mask, gamma, beta, Wa, ba, Wb, bb);
    norm_kernel<<<NRES, NRES>>>(mask);
    wconv_kernel<<<512, 256>>>(Wo);
    gemm1_kernel<<<dim3(96, 96), 256, G1_SMEM>>>();
    gemm2_kernel<<<NPAIR/128, 256, G2_SMEM>>>(Zraw, bo, out);
}

// round 6
// speedup vs baseline: 1.2688x; 1.2688x over previous
#include <cuda_runtime.h>
#include <cuda_bf16.h>
#include <cstdint>

#define NRES  384
#define NSEQ  256
#define NFEAT 64
#define NPROJ 32
#define NOUT  128
#define ICDIM (NRES*NPROJ)          // 12288
#define NPAIR (NRES*NRES)           // 147456
#define CD    (NPROJ*NPROJ)         // 1024
#define LN_EPS 1e-5f

// ------------------------- scratch (device globals) -------------------------
__device__ __nv_bfloat16 g_Lt[(size_t)ICDIM*NSEQ];   // [m=(i,c)][s]  K-major
__device__ __nv_bfloat16 g_Rt[(size_t)ICDIM*NSEQ];   // [n=(j,d)][s]  K-major
__device__ __nv_bfloat16 g_O [(size_t)NPAIR*CD];     // [(i,j)][(c,d)]
__device__ __nv_bfloat16 g_Wob[NOUT*CD];             // Wo bf16 [o][cd]
__device__ float         g_normv[NPAIR];

// ------------------------- helpers -------------------------
__device__ __forceinline__ uint32_t smem_u32(const void* p){
    uint32_t a;
    asm("{ .reg .u64 t; cvta.to.shared.u64 t, %1; cvt.u32.u64 %0, t; }":"=r"(a):"l"(p));
    return a;
}
__device__ __forceinline__ void ldsm4(uint32_t& r0, uint32_t& r1, uint32_t& r2, uint32_t& r3, uint32_t a){
    asm volatile("ldmatrix.sync.aligned.m8n8.x4.shared.b16 {%0,%1,%2,%3}, [%4];"
        : "=r"(r0),"=r"(r1),"=r"(r2),"=r"(r3) : "r"(a));
}
__device__ __forceinline__ void mma16816(float* c, const uint32_t* a, uint32_t b0, uint32_t b1){
    asm volatile("mma.sync.aligned.m16n8k16.row.col.f32.bf16.bf16.f32 "
        "{%0,%1,%2,%3}, {%4,%5,%6,%7}, {%8,%9}, {%0,%1,%2,%3};"
        : "+f"(c[0]),"+f"(c[1]),"+f"(c[2]),"+f"(c[3])
        : "r"(a[0]),"r"(a[1]),"r"(a[2]),"r"(a[3]),"r"(b0),"r"(b1));
}
__device__ __forceinline__ uint32_t packbf2(float a, float b){
    __nv_bfloat162 h = __floats2bfloat162_rn(a, b);
    return *(uint32_t*)&h;
}
#define CP16(dst, src) asm volatile("cp.async.cg.shared.global [%0], [%1], 16;" \
    :: "r"(dst), "l"(src) : "memory")
#define CP_COMMIT() asm volatile("cp.async.commit_group;" ::: "memory")
#define CP_WAIT(n)  asm volatile("cp.async.wait_group %0;" :: "n"(n) : "memory")

// ---------------------------------------------------------------------------
// prep: LN + projections + mask; write transposed bf16 g_Lt/g_Rt.
// grid=384 (block per residue i), 256 threads (thread per s).
// ---------------------------------------------------------------------------
#define PREP_SMEM (4096*4 + 2*8192*2)   // 49152
__global__ void __launch_bounds__(256,2)
prep_kernel(const float* __restrict__ M, const float* __restrict__ mask,
            const float* __restrict__ gamma, const float* __restrict__ beta,
            const float* __restrict__ Wa, const float* __restrict__ ba,
            const float* __restrict__ Wb, const float* __restrict__ bb)
{
    extern __shared__ float ps[];
    float* sWa = ps;
    float* sWb = ps + 2048;
    __nv_bfloat16* sLb = (__nv_bfloat16*)(ps + 4096);  // [32][256]
    __nv_bfloat16* sRb = sLb + 8192;

    const int i = blockIdx.x;
    const int tid = threadIdx.x;
    for (int u = tid; u < NPROJ*NFEAT; u += 256){ sWa[u] = Wa[u]; sWb[u] = Wb[u]; }

    const int s = tid;
    const float4* mr = (const float4*)(M + ((size_t)s*NRES + i)*NFEAT);
    float4 mn[16];
    float s1 = 0.f, s2 = 0.f;
    #pragma unroll
    for (int q = 0; q < 16; q++){
        float4 v = mr[q]; mn[q] = v;
        s1 += v.x + v.y + v.z + v.w;
        s2 += v.x*v.x + v.y*v.y + v.z*v.z + v.w*v.w;
    }
    float mu  = s1 * (1.f/64.f);
    float var = s2 * (1.f/64.f) - mu*mu;
    float inv = rsqrtf(var + LN_EPS);
    const float4* g4 = (const float4*)gamma;
    const float4* b4 = (const float4*)beta;
    #pragma unroll
    for (int q = 0; q < 16; q++){
        float4 gg = g4[q], be = b4[q];
        mn[q].x = (mn[q].x - mu)*inv*gg.x + be.x;
        mn[q].y = (mn[q].y - mu)*inv*gg.y + be.y;
        mn[q].z = (mn[q].z - mu)*inv*gg.z + be.z;
        mn[q].w = (mn[q].w - mu)*inv*gg.w + be.w;
    }
    const float msk = mask[(size_t)s*NRES + i];
    __syncthreads();

    #pragma unroll 4
    for (int c = 0; c < NPROJ; c++){
        float accA = ba[c], accB = bb[c];
        const float4* wa = (const float4*)(sWa + c*NFEAT);
        const float4* wb = (const float4*)(sWb + c*NFEAT);
        #pragma unroll
        for (int q = 0; q < 16; q++){
            float4 w1 = wa[q], w2 = wb[q], v = mn[q];
            accA += v.x*w1.x + v.y*w1.y + v.z*w1.z + v.w*w1.w;
            accB += v.x*w2.x + v.y*w2.y + v.z*w2.z + v.w*w2.w;
        }
        sLb[c*256 + s] = __float2bfloat16(msk*accA);
        sRb[c*256 + s] = __float2bfloat16(msk*accB);
    }
    __syncthreads();

    for (int u = tid; u < NPROJ*128; u += 256){
        int c = u >> 7, sp = (u & 127) << 1;
        *(uint32_t*)(g_Lt + ((size_t)(i*NPROJ + c))*NSEQ + sp) = *(const uint32_t*)(sLb + c*256 + sp);
        *(uint32_t*)(g_Rt + ((size_t)(i*NPROJ + c))*NSEQ + sp) = *(const uint32_t*)(sRb + c*256 + sp);
    }
}

// ---------------------------------------------------------------------------
__global__ void norm_kernel(const float* __restrict__ mask)
{
    const int i = blockIdx.x, j = threadIdx.x;
    float acc = 0.0f;
    for (int s = 0; s < NSEQ; s++)
        acc += mask[s*NRES + i] * mask[s*NRES + j];
    g_normv[i*NRES + j] = acc;
}

__global__ void wconv_kernel(const float* __restrict__ Wo)
{
    int idx = blockIdx.x*256 + threadIdx.x;
    g_Wob[idx] = __float2bfloat16(Wo[idx]);
}

// ---------------------------------------------------------------------------
// gemm1: O[128x128] = Lt[it*128..] @ Rt[jt*128..]^T, K=256.
// 128 threads, 4 warps, 64x64 warp tiles. 3-stage cp.async ring (96KB), occ 2.
// ---------------------------------------------------------------------------
#define G1_SMEM (3*32768)
__global__ void __launch_bounds__(128,2) gemm1_kernel()
{
    extern __shared__ char sm1[];
    const int tid = threadIdx.x, lane = tid & 31, w = tid >> 5;
    const int it = blockIdx.y, jt = blockIdx.x;
    const int wr = w >> 1, wc = w & 1;
    const int m0 = wr*64, n0 = wc*64;
    const int lo7 = lane & 7, hi = lane >> 4, l15 = lane & 15;

    const uint32_t sb = smem_u32(sm1);
    const int lrb = tid >> 3;        // 0..15
    const int lc  = tid & 7;         // 16B-unit col 0..7

    #define G1_LOAD(kc, s) do {                                               \
        _Pragma("unroll")                                                     \
        for (int q = 0; q < 8; q++){                                          \
            int row = q*16 + lrb;                                             \
            int cp = lc ^ (row & 7);                                          \
            uint32_t da = sb + (s)*32768 + row*128 + cp*16;                   \
            CP16(da,         (const void*)(g_Lt + ((size_t)(it*128 + row))*NSEQ + (kc)*64 + lc*8)); \
            CP16(da + 16384, (const void*)(g_Rt + ((size_t)(jt*128 + row))*NSEQ + (kc)*64 + lc*8)); \
        }                                                                     \
    } while(0)

    float acc[4][8][4];
    #pragma unroll
    for (int a = 0; a < 4; a++)
        #pragma unroll
        for (int b = 0; b < 8; b++)
            #pragma unroll
            for (int c = 0; c < 4; c++) acc[a][b][c] = 0.f;

    G1_LOAD(0, 0); CP_COMMIT();
    G1_LOAD(1, 1); CP_COMMIT();

    #pragma unroll 1
    for (int kc = 0; kc < 4; kc++){
        if (kc + 2 < 4){ G1_LOAD(kc+2, (kc+2)%3); CP_COMMIT(); CP_WAIT(2); }
        else if (kc + 1 < 4){ CP_WAIT(1); }
        else { CP_WAIT(0); }
        __syncthreads();
        const uint32_t sA = sb + (kc%3)*32768;
        const uint32_t sB = sA + 16384;
        #pragma unroll
        for (int ks = 0; ks < 4; ks++){
            int ch = ((ks*2 + hi) ^ lo7) << 4;
            uint32_t a[4][4], b[4][4];
            #pragma unroll
            for (int mt = 0; mt < 4; mt++)
                ldsm4(a[mt][0],a[mt][1],a[mt][2],a[mt][3],
                      sA + (m0 + mt*16 + l15)*128 + ch);
            #pragma unroll
            for (int nb = 0; nb < 4; nb++)
                ldsm4(b[nb][0],b[nb][1],b[nb][2],b[nb][3],
                      sB + (n0 + nb*16 + l15)*128 + ch);
            #pragma unroll
            for (int mt = 0; mt < 4; mt++){
                #pragma unroll
                for (int nb = 0; nb < 4; nb++){
                    mma16816(acc[mt][nb*2],   a[mt], b[nb][0], b[nb][2]);
                    mma16816(acc[mt][nb*2+1], a[mt], b[nb][1], b[nb][3]);
                }
            }
        }
        __syncthreads();
    }

    // epilogue -> g_O[(i*384+j)*1024 + c*32 + d] bf16
    const int rbase = lane >> 2, cpair = (lane & 3)*2;
    #pragma unroll
    for (int mt = 0; mt < 4; mt++){
        int mg0 = it*128 + m0 + mt*16 + rbase;
        int mg1 = mg0 + 8;
        #pragma unroll
        for (int nt = 0; nt < 8; nt++){
            int ncol = n0 + nt*8 + cpair;
            int j = jt*4 + (ncol >> 5);
            int d = ncol & 31;
            size_t base0 = (((size_t)(mg0 >> 5)*NRES + j) << 10) + ((mg0 & 31) << 5) + d;
            size_t base1 = (((size_t)(mg1 >> 5)*NRES + j) << 10) + ((mg1 & 31) << 5) + d;
            *(uint32_t*)(g_O + base0) = packbf2(acc[mt][nt][0], acc[mt][nt][1]);
            *(uint32_t*)(g_O + base1) = packbf2(acc[mt][nt][2], acc[mt][nt][3]);
        }
    }
}

// ---------------------------------------------------------------------------
// gemm2: Z[m,o] = sum_k O[m,k]*Wob[o,k], m-tile 128, o=128, K=1024.
// 128 threads, 4 warps, 64x64 warp tiles, 3-stage cp.async. Fused epilogue.
// ---------------------------------------------------------------------------
#define G2_SMEM (3*32768)
__global__ void __launch_bounds__(128,2)
gemm2_kernel(const float* __restrict__ Zraw, const float* __restrict__ bo,
             float* __restrict__ out)
{
    extern __shared__ char sm2[];
    __shared__ float sbo[NOUT];
    const int tid = threadIdx.x, lane = tid & 31, w = tid >> 5;
    const int m0 = blockIdx.x * 128;
    const int wr = w >> 1, wc = w & 1;
    const int mw0 = wr*64, o0 = wc*64;
    const int lo7 = lane & 7, hi = lane >> 4, l15 = lane & 15;

    const uint32_t sb = smem_u32(sm2);
    if (tid < NOUT) sbo[tid] = bo[tid];

    const int lrb = tid >> 3;
    const int lc  = tid & 7;

    #define G2_LOAD(kc, s) do {                                               \
        _Pragma("unroll")                                                     \
        for (int q = 0; q < 8; q++){                                          \
            int row = q*16 + lrb;                                             \
            int cp = lc ^ (row & 7);                                          \
            uint32_t da = sb + (s)*32768 + row*128 + cp*16;                   \
            CP16(da,         (const void*)(g_O   + (size_t)(m0 + row)*CD + (kc)*64 + lc*8)); \
            CP16(da + 16384, (const void*)(g_Wob + (size_t)row*CD        + (kc)*64 + lc*8)); \
        }                                                                     \
    } while(0)

    float acc[4][8][4];
    #pragma unroll
    for (int a = 0; a < 4; a++)
        #pragma unroll
        for (int b = 0; b < 8; b++)
            #pragma unroll
            for (int c = 0; c < 4; c++) acc[a][b][c] = 0.f;

    G2_LOAD(0, 0); CP_COMMIT();
    G2_LOAD(1, 1); CP_COMMIT();

    #pragma unroll 1
    for (int kc = 0; kc < 16; kc++){
        if (kc + 2 < 16){ G2_LOAD(kc+2, (kc+2)%3); CP_COMMIT(); CP_WAIT(2); }
        else if (kc + 1 < 16){ CP_WAIT(1); }
        else { CP_WAIT(0); }
        __syncthreads();
        const uint32_t sA = sb + (kc%3)*32768;
        const uint32_t sB = sA + 16384;
        #pragma unroll
        for (int ks = 0; ks < 4; ks++){
            int ch = ((ks*2 + hi) ^ lo7) << 4;
            uint32_t a[4][4], b[4][4];
            #pragma unroll
            for (int mt = 0; mt < 4; mt++)
                ldsm4(a[mt][0],a[mt][1],a[mt][2],a[mt][3],
                      sA + (mw0 + mt*16 + l15)*128 + ch);
            #pragma unroll
            for (int nb = 0; nb < 4; nb++)
                ldsm4(b[nb][0],b[nb][1],b[nb][2],b[nb][3],
                      sB + (o0 + nb*16 + l15)*128 + ch);
            #pragma unroll
            for (int mt = 0; mt < 4; mt++){
                #pragma unroll
                for (int nb = 0; nb < 4; nb++){
                    mma16816(acc[mt][nb*2],   a[mt], b[nb][0], b[nb][2]);
                    mma16816(acc[mt][nb*2+1], a[mt], b[nb][1], b[nb][3]);
                }
            }
        }
        __syncthreads();
    }

    // fused epilogue: (z+bo)*invn + Zraw
    const int rbase = lane >> 2, cpair = (lane & 3)*2;
    #pragma unroll
    for (int mt = 0; mt < 4; mt++){
        int mA = m0 + mw0 + mt*16 + rbase;
        int mB = mA + 8;
        float invA = 1.0f / (0.001f + g_normv[mA]);
        float invB = 1.0f / (0.001f + g_normv[mB]);
        #pragma unroll
        for (int nt = 0; nt < 8; nt++){
            int o = o0 + nt*8 + cpair;
            float b0 = sbo[o], b1 = sbo[o+1];
            float2 zA = *(const float2*)(Zraw + (size_t)mA*NOUT + o);
            float2 zB = *(const float2*)(Zraw + (size_t)mB*NOUT + o);
            float2 rA, rB;
            rA.x = (acc[mt][nt][0] + b0)*invA + zA.x;
            rA.y = (acc[mt][nt][1] + b1)*invA + zA.y;
            rB.x = (acc[mt][nt][2] + b0)*invB + zB.x;
            rB.y = (acc[mt][nt][3] + b1)*invB + zB.y;
            *(float2*)(out + (size_t)mA*NOUT + o) = rA;
            *(float2*)(out + (size_t)mB*NOUT + o) = rB;
        }
    }
}

// ---------------------------------------------------------------------------
extern "C" void kernel_launch(void* const* d_in, const int* in_sizes, int n_in,
                              void* d_out, int out_size)
{
    const float* M     = (const float*)d_in[0];
    const float* mask  = (const float*)d_in[1];
    const float* Zraw  = (const float*)d_in[2];
    const float* gamma = (const float*)d_in[3];
    const float* beta  = (const float*)d_in[4];
    const float* Wa    = (const float*)d_in[5];
    const float* ba    = (const float*)d_in[6];
    const float* Wb    = (const float*)d_in[7];
    const float* bb    = (const float*)d_in[8];
    const float* Wo    = (const float*)d_in[9];
    const float* bo    = (const float*)d_in[10];
    float* out = (float*)d_out;

    cudaFuncSetAttribute(prep_kernel,  cudaFuncAttributeMaxDynamicSharedMemorySize, PREP_SMEM);
    cudaFuncSetAttribute(gemm1_kernel, cudaFuncAttributeMaxDynamicSharedMemorySize, G1_SMEM);
    cudaFuncSetAttribute(gemm2_kernel, cudaFuncAttributeMaxDynamicSharedMemorySize, G2_SMEM);

    prep_kernel<<<NRES, 256, PREP_SMEM>>>(M, mask, gamma, beta, Wa, ba, Wb, bb);
    norm_kernel<<<NRES, NRES>>>(mask);
    wconv_kernel<<<512, 256>>>(Wo);
    gemm1_kernel<<<dim3(96, 96), 128, G1_SMEM>>>();
    gemm2_kernel<<<NPAIR/128, 128, G2_SMEM>>>(Zraw, bo, out);
}